// round 1
// baseline (speedup 1.0000x reference)
#include <cuda_runtime.h>
#include <math.h>

#define B_   2
#define S_   2048
#define D_   512
#define L_   4
#define H_   8
#define DH   64
#define M_   (B_*S_)      // 4096 rows
#define DI   512          // H*DH
#define QKVN 1536
#define DHID 1365

// ---------------- scratch (no allocation allowed) ----------------
__device__ float g_t   [M_ * D_];          // residual stream
__device__ float g_x   [M_ * D_];          // normed activations
__device__ float g_qkv [M_ * QKVN];        // q|k|v packed per row
__device__ float g_fv  [M_ * DI];          // first layer's v
__device__ float g_o   [M_ * DI];          // attention output
__device__ float g_h   [M_ * 2 * DHID];    // ff_in output
__device__ float g_y1  [M_ * DHID];        // gated gelu output

// ---------------- elementwise copy ----------------
__global__ void copy_k(const float4* __restrict__ in, float4* __restrict__ out, int n4) {
    int i = blockIdx.x * blockDim.x + threadIdx.x;
    if (i < n4) out[i] = in[i];
}

// ---------------- rmsnorm: one block per row of 512 ----------------
__global__ void rmsnorm_k(const float* __restrict__ in, const float* __restrict__ w,
                          float* __restrict__ out) {
    int row = blockIdx.x;
    const float4* ip = (const float4*)(in + (size_t)row * D_);
    float4 v = ip[threadIdx.x];                       // 128 threads * 4 = 512
    float ss = v.x*v.x + v.y*v.y + v.z*v.z + v.w*v.w;
    #pragma unroll
    for (int o = 16; o; o >>= 1) ss += __shfl_xor_sync(0xffffffffu, ss, o);
    __shared__ float sred[4];
    if ((threadIdx.x & 31) == 0) sred[threadIdx.x >> 5] = ss;
    __syncthreads();
    float tot = sred[0] + sred[1] + sred[2] + sred[3];
    float sc = rsqrtf(tot * (1.0f / 512.0f) + 1.1920929e-7f);
    const float4* wp = (const float4*)w;
    float4 wv = wp[threadIdx.x];
    float4 o4;
    o4.x = v.x * sc * wv.x; o4.y = v.y * sc * wv.y;
    o4.z = v.z * sc * wv.z; o4.w = v.w * sc * wv.w;
    ((float4*)(out + (size_t)row * D_))[threadIdx.x] = o4;
}

// ---------------- generic SGEMM: C[M,N] = A[M,K]@B[K,N] (+bias)(+add) ----------------
// BM=BN=128, BK=16, 256 threads, 8x8 per thread. M must be a multiple of 128 (it is: 4096).
__global__ void sgemm128(int M, int N, int K,
                         const float* __restrict__ A, const float* __restrict__ B,
                         float* __restrict__ C, const float* __restrict__ bias,
                         const float* __restrict__ addsrc) {
    __shared__ float As[16][128];
    __shared__ float Bs[16][128];
    int tid = threadIdx.x;
    int tx = tid & 15, ty = tid >> 4;
    int m0 = blockIdx.y * 128, n0 = blockIdx.x * 128;

    float acc[8][8];
    #pragma unroll
    for (int i = 0; i < 8; i++)
        #pragma unroll
        for (int j = 0; j < 8; j++) acc[i][j] = 0.0f;

    int am = tid >> 1;           // 0..127 row in tile
    int ak = (tid & 1) * 8;      // 0 or 8
    int bn = tid & 127;          // col in tile
    int bk = (tid >> 7) * 8;     // 0 or 8

    for (int k0 = 0; k0 < K; k0 += 16) {
        #pragma unroll
        for (int i = 0; i < 8; i++) {
            int kk = k0 + ak + i;
            As[ak + i][am] = (kk < K) ? A[(size_t)(m0 + am) * K + kk] : 0.0f;
        }
        bool ncol = (n0 + bn) < N;
        #pragma unroll
        for (int i = 0; i < 8; i++) {
            int kk = k0 + bk + i;
            Bs[bk + i][bn] = (kk < K && ncol) ? B[(size_t)kk * N + n0 + bn] : 0.0f;
        }
        __syncthreads();
        #pragma unroll
        for (int kk = 0; kk < 16; kk++) {
            float a[8], b[8];
            #pragma unroll
            for (int i = 0; i < 8; i++) a[i] = As[kk][ty * 8 + i];
            #pragma unroll
            for (int j = 0; j < 8; j++) b[j] = Bs[kk][tx * 8 + j];
            #pragma unroll
            for (int i = 0; i < 8; i++)
                #pragma unroll
                for (int j = 0; j < 8; j++) acc[i][j] += a[i] * b[j];
        }
        __syncthreads();
    }
    #pragma unroll
    for (int i = 0; i < 8; i++) {
        int row = m0 + ty * 8 + i;
        #pragma unroll
        for (int j = 0; j < 8; j++) {
            int col = n0 + tx * 8 + j;
            if (col < N) {
                float v = acc[i][j];
                if (bias)   v += bias[col];
                if (addsrc) v += addsrc[(size_t)row * N + col];
                C[(size_t)row * N + col] = v;
            }
        }
    }
}

// ---------------- save first-layer v ----------------
__global__ void savefv_k(const float* __restrict__ qkv, float* __restrict__ fv) {
    int idx = blockIdx.x * blockDim.x + threadIdx.x;   // < M_*512
    int row = idx >> 9, c = idx & 511;
    fv[idx] = qkv[(size_t)row * QKVN + 1024 + c];
}

// ---------------- v-mix (l>0): one warp per (row, head) ----------------
__global__ void vmix_k(const float* __restrict__ x, const float* __restrict__ mw,
                       const float* __restrict__ mb, float* __restrict__ qkv,
                       const float* __restrict__ fv) {
    int row = blockIdx.x;
    int lane = threadIdx.x & 31;
    int h = threadIdx.x >> 5;     // 0..7 (blockDim = 256)
    float dot = 0.0f;
    #pragma unroll
    for (int d = lane; d < 512; d += 32) dot += x[(size_t)row * 512 + d] * mw[d * 8 + h];
    #pragma unroll
    for (int o = 16; o; o >>= 1) dot += __shfl_xor_sync(0xffffffffu, dot, o);
    float mix = 1.0f / (1.0f + expf(-(dot + mb[h])));
    #pragma unroll
    for (int d = lane; d < 64; d += 32) {
        size_t vi = (size_t)row * QKVN + 1024 + h * 64 + d;
        float v = qkv[vi];
        float f = fv[(size_t)row * 512 + h * 64 + d];
        qkv[vi] = v + mix * (f - v);
    }
}

// ---------------- RoPE on q and k ----------------
__global__ void rope_k(float* __restrict__ qkv) {
    int idx = blockIdx.x * blockDim.x + threadIdx.x;   // < M_*H_*32
    int pair = idx & 31;
    int h    = (idx >> 5) & 7;
    int row  = idx >> 8;
    int pos  = row & (S_ - 1);
    float inv = expf(-logf(10000.0f) * (float)pair * (1.0f / 32.0f));
    float f = (float)pos * inv;
    float s, c;
    sincosf(f, &s, &c);
    size_t base = (size_t)row * QKVN + h * 64 + 2 * pair;
    float q1 = qkv[base], q2 = qkv[base + 1];
    qkv[base]     = q1 * c - q2 * s;
    qkv[base + 1] = q1 * s + q2 * c;
    float k1 = qkv[base + 512], k2 = qkv[base + 513];
    qkv[base + 512] = k1 * c - k2 * s;
    qkv[base + 513] = k1 * s + k2 * c;
}

// ---------------- block-causal flash attention ----------------
// grid (64 qblocks, B*H), 128 threads. Query block qi attends key blocks 0..qi fully.
__global__ void attn_k(const float* __restrict__ qkv, float* __restrict__ o) {
    int qi = blockIdx.x;
    int h  = blockIdx.y & 7;
    int b  = blockIdx.y >> 3;
    __shared__ float Qs[32][65];
    __shared__ float Ks[32][65];
    __shared__ float Vs[32][65];
    int tid = threadIdx.x;
    int row0 = b * S_ + qi * 32;

    #pragma unroll
    for (int i = 0; i < 16; i++) {
        int e = i * 128 + tid;
        int r = e >> 6, d = e & 63;
        Qs[r][d] = qkv[(size_t)(row0 + r) * QKVN + h * 64 + d] * 0.125f;  // scale = Dh^-0.5
    }

    int r = tid >> 2, cg = tid & 3;
    int lane = tid & 31;
    float m_prev = -INFINITY, lsum = 0.0f;
    float O[16];
    #pragma unroll
    for (int i = 0; i < 16; i++) O[i] = 0.0f;

    for (int j = 0; j <= qi; j++) {
        __syncthreads();
        int krow0 = b * S_ + j * 32;
        #pragma unroll
        for (int i = 0; i < 16; i++) {
            int e = i * 128 + tid;
            int rr = e >> 6, d = e & 63;
            size_t base = (size_t)(krow0 + rr) * QKVN + h * 64 + d;
            Ks[rr][d] = qkv[base + 512];
            Vs[rr][d] = qkv[base + 1024];
        }
        __syncthreads();

        float sc[8];
        #pragma unroll
        for (int c = 0; c < 8; c++) {
            float s = 0.0f;
            #pragma unroll
            for (int k = 0; k < 64; k++) s += Qs[r][k] * Ks[cg * 8 + c][k];
            sc[c] = s;
        }
        float mx = sc[0];
        #pragma unroll
        for (int c = 1; c < 8; c++) mx = fmaxf(mx, sc[c]);
        mx = fmaxf(mx, __shfl_xor_sync(0xffffffffu, mx, 1));
        mx = fmaxf(mx, __shfl_xor_sync(0xffffffffu, mx, 2));
        float m_new = fmaxf(m_prev, mx);
        float alpha = __expf(m_prev - m_new);

        float p[8];
        float psum = 0.0f;
        #pragma unroll
        for (int c = 0; c < 8; c++) { p[c] = __expf(sc[c] - m_new); psum += p[c]; }
        lsum = lsum * alpha + psum;
        #pragma unroll
        for (int d = 0; d < 16; d++) O[d] *= alpha;

        #pragma unroll
        for (int c = 0; c < 32; c++) {
            float pc = __shfl_sync(0xffffffffu, p[c & 7], (lane & ~3) | (c >> 3));
            #pragma unroll
            for (int d = 0; d < 16; d++) O[d] += pc * Vs[c][cg * 16 + d];
        }
        m_prev = m_new;
    }
    lsum += __shfl_xor_sync(0xffffffffu, lsum, 1);
    lsum += __shfl_xor_sync(0xffffffffu, lsum, 2);
    float inv = 1.0f / lsum;
    size_t ob = (size_t)(row0 + r) * 512 + h * 64 + cg * 16;
    #pragma unroll
    for (int d = 0; d < 16; d++) o[ob + d] = O[d] * inv;
}

// ---------------- gated exact GELU ----------------
__global__ void gelu_k(const float* __restrict__ hb, float* __restrict__ y1) {
    int idx = blockIdx.x * blockDim.x + threadIdx.x;
    if (idx >= M_ * DHID) return;
    int row = idx / DHID;
    int j   = idx - row * DHID;
    float a = hb[(size_t)row * (2 * DHID) + j];
    float g = hb[(size_t)row * (2 * DHID) + DHID + j];
    float ge = 0.5f * g * (1.0f + erff(g * 0.70710678118654752f));
    y1[idx] = a * ge;
}

// ---------------- launch ----------------
extern "C" void kernel_launch(void* const* d_in, const int* in_sizes, int n_in,
                              void* d_out, int out_size) {
    const float* tokens       = (const float*)d_in[0];
    const float* attn_norm_w  = (const float*)d_in[1];
    const float* qkv_w        = (const float*)d_in[2];
    const float* out_w        = (const float*)d_in[3];
    const float* mix_w        = (const float*)d_in[4];
    const float* mix_b        = (const float*)d_in[5];
    const float* ff_norm_w    = (const float*)d_in[6];
    const float* ff_in_w      = (const float*)d_in[7];
    const float* ff_in_b      = (const float*)d_in[8];
    const float* ff_out_w     = (const float*)d_in[9];
    const float* ff_out_b     = (const float*)d_in[10];
    const float* final_norm_w = (const float*)d_in[11];

    float *t_, *x_, *qkv_, *fv_, *o_, *h_, *y1_;
    cudaGetSymbolAddress((void**)&t_,   g_t);
    cudaGetSymbolAddress((void**)&x_,   g_x);
    cudaGetSymbolAddress((void**)&qkv_, g_qkv);
    cudaGetSymbolAddress((void**)&fv_,  g_fv);
    cudaGetSymbolAddress((void**)&o_,   g_o);
    cudaGetSymbolAddress((void**)&h_,   g_h);
    cudaGetSymbolAddress((void**)&y1_,  g_y1);

    copy_k<<<(M_ * D_ / 4 + 255) / 256, 256>>>((const float4*)tokens, (float4*)t_, M_ * D_ / 4);

    for (int l = 0; l < L_; l++) {
        rmsnorm_k<<<M_, 128>>>(t_, attn_norm_w + l * D_, x_);

        sgemm128<<<dim3(QKVN / 128, M_ / 128), 256>>>(
            M_, QKVN, D_, x_, qkv_w + (size_t)l * D_ * QKVN, qkv_, nullptr, nullptr);

        if (l == 0)
            savefv_k<<<(M_ * DI) / 256, 256>>>(qkv_, fv_);
        else
            vmix_k<<<M_, 256>>>(x_, mix_w + (size_t)l * D_ * H_, mix_b + l * H_, qkv_, fv_);

        rope_k<<<M_, 256>>>(qkv_);

        attn_k<<<dim3(S_ / 32, B_ * H_), 128>>>(qkv_, o_);

        sgemm128<<<dim3(D_ / 128, M_ / 128), 256>>>(
            M_, D_, DI, o_, out_w + (size_t)l * DI * D_, t_, nullptr, t_);

        rmsnorm_k<<<M_, 128>>>(t_, ff_norm_w + l * D_, x_);

        sgemm128<<<dim3((2 * DHID + 127) / 128, M_ / 128), 256>>>(
            M_, 2 * DHID, D_, x_, ff_in_w + (size_t)l * D_ * 2 * DHID, h_,
            ff_in_b + (size_t)l * 2 * DHID, nullptr);

        gelu_k<<<(M_ * DHID + 255) / 256, 256>>>(h_, y1_);

        sgemm128<<<dim3(D_ / 128, M_ / 128), 256>>>(
            M_, D_, DHID, y1_, ff_out_w + (size_t)l * DHID * D_, t_,
            ff_out_b + (size_t)l * D_, t_);
    }

    rmsnorm_k<<<M_, 128>>>(t_, final_norm_w, (float*)d_out);
}